// round 14
// baseline (speedup 1.0000x reference)
#include <cuda_runtime.h>
#include <cuda_bf16.h>
#include <math.h>
#include <stdint.h>

// Problem constants (fixed by setup_inputs)
#define NBATCH 2
#define NPB_NODES 20000
#define BN (NBATCH * NPB_NODES)   // 40000
#define KNB 32
#define H 128
#define C 40
#define NPW 8
#define NGROUPS (BN / NPW)

#define THREADS_EMB 256
#define THREADS_GAT 512
#define THREADS_CLS 512
#define NWARPS_CLS  16
#define GRID 148
#define TOTAL_WARPS_CLS (GRID * NWARPS_CLS)

// Scratch buffers
__device__ float g_h0[BN * H];
__device__ float g_h1[BN * H];
__device__ float g_y [BN * H];
__device__ float g_u [BN * H];

// packed f32x2 helpers (FFMA kernels)
#define FMA2(acc, a, b) asm("fma.rn.f32x2 %0, %1, %2, %0;" : "+l"(acc) : "l"(a), "l"(b))
#define PACK2(d, s)     asm("mov.b64 %0, {%1, %1};" : "=l"(d) : "f"(s))
#define UNPACK2(lo, hi, s) asm("mov.b64 {%0, %1}, %2;" : "=f"(lo), "=f"(hi) : "l"(s))

__device__ __forceinline__ uint32_t smem_to_u32(const void* p) {
    uint32_t a;
    asm("{ .reg .u64 t; cvta.to.shared.u64 t, %1; cvt.u32.u64 %0, t; }" : "=r"(a) : "l"(p));
    return a;
}
__device__ __forceinline__ void ldsm_x4(uint32_t& r0, uint32_t& r1, uint32_t& r2, uint32_t& r3,
                                        uint32_t addr) {
    asm volatile("ldmatrix.sync.aligned.m8n8.x4.shared.b16 {%0,%1,%2,%3}, [%4];"
                 : "=r"(r0), "=r"(r1), "=r"(r2), "=r"(r3) : "r"(addr));
}
__device__ __forceinline__ void mma_bf16(float* c,
                                         uint32_t a0, uint32_t a1, uint32_t a2, uint32_t a3,
                                         uint32_t b0, uint32_t b1) {
    asm volatile("mma.sync.aligned.m16n8k16.row.col.f32.bf16.bf16.f32 "
                 "{%0,%1,%2,%3}, {%4,%5,%6,%7}, {%8,%9}, {%0,%1,%2,%3};"
                 : "+f"(c[0]), "+f"(c[1]), "+f"(c[2]), "+f"(c[3])
                 : "r"(a0), "r"(a1), "r"(a2), "r"(a3), "r"(b0), "r"(b1));
}
__device__ __forceinline__ uint32_t bfpair(__nv_bfloat16 a, __nv_bfloat16 b) {
    __nv_bfloat162 t; t.x = a; t.y = b;
    return *reinterpret_cast<uint32_t*>(&t);
}

// ---------------------------------------------------------------------------
// Tensor GEMM (mma.sync bf16x3): Y = h@W, U = h@B.
// Persistent CTAs; tile = 128 nodes x 256 dims; 16 warps, warp tile 32x64.
// smem rows padded to 272B (17x16B) -> conflict-free ldmatrix.
//   Whi [256][128]bf16 @0       (69632 B)
//   Wlo                 @69632  (69632 B)
//   Ahi [128][128]bf16  @139264 (34816 B)
//   Alo                 @174080 (34816 B)   total 208896 B
// ---------------------------------------------------------------------------
#define GT 512
#define SM_WHI 0
#define SM_WLO 69632
#define SM_AHI 139264
#define SM_ALO 174080
#define GEMM_SMEM 208896

extern "C" __global__ void __launch_bounds__(GT, 1)
gemm_mma_kernel(const float* __restrict__ hin,
                const float* __restrict__ Wp, const float* __restrict__ Bp,
                float* __restrict__ Yp, float* __restrict__ Up)
{
    extern __shared__ char smem[];
    const uint32_t sb = smem_to_u32(smem);
    const int tid  = threadIdx.x;
    const int lane = tid & 31;
    const int w    = tid >> 5;

    // ---- Stage weights as K-major bf16 hi/lo: Wop[d][k]; d<128 = W(Y), d>=128 = B(U)
    for (int l = tid; l < 128 * 128; l += GT) {
        int k = l >> 7, d = l & 127;               // coalesced read Wp[l] = W[k][d]
        float wv = Wp[l];
        __nv_bfloat16 hi = __float2bfloat16(wv);
        *(__nv_bfloat16*)(smem + SM_WHI + d * 272 + k * 2) = hi;
        *(__nv_bfloat16*)(smem + SM_WLO + d * 272 + k * 2) =
            __float2bfloat16(wv - __bfloat162float(hi));
        float bv = Bp[l];
        hi = __float2bfloat16(bv);
        *(__nv_bfloat16*)(smem + SM_WHI + (128 + d) * 272 + k * 2) = hi;
        *(__nv_bfloat16*)(smem + SM_WLO + (128 + d) * 272 + k * 2) =
            __float2bfloat16(bv - __bfloat162float(hi));
    }
    __syncthreads();

    const float4* h4 = (const float4*)hin;
    const int mrow = (w & 3) * 32;     // warp m offset within tile
    const int ncol = (w >> 2) * 64;    // warp n offset (0,64 -> Y; 128,192 -> U)

    // per-lane ldmatrix relative offsets
    const uint32_t aRel0 = (uint32_t)((mrow + ((lane >> 3) & 1) * 8 + (lane & 7)) * 272
                                      + (lane >> 4) * 16);
    const uint32_t aRel1 = aRel0 + 16 * 272;
    uint32_t bRel[4];
    #pragma unroll
    for (int g = 0; g < 4; g++)
        bRel[g] = (uint32_t)((ncol + g * 16 + ((lane >> 4) & 1) * 8 + (lane & 7)) * 272
                             + ((lane >> 3) & 1) * 16);

    float* const outb = (ncol < 128) ? Yp : Up;
    const int dbase = ncol & 127;
    const int r = lane >> 2, cc = (lane & 3) * 2;

    for (int tb = blockIdx.x * 128; tb < BN; tb += gridDim.x * 128) {
        // ---- Stage A tile (hi/lo bf16) ----
        for (int l = tid; l < 128 * 32; l += GT) {
            int row = l >> 5, c4 = l & 31;
            int node = tb + row;
            float4 v = (node < BN) ? h4[node * 32 + c4] : make_float4(0.f, 0.f, 0.f, 0.f);
            __nv_bfloat16 h0 = __float2bfloat16(v.x), h1 = __float2bfloat16(v.y);
            __nv_bfloat16 h2 = __float2bfloat16(v.z), h3 = __float2bfloat16(v.w);
            uint2 hiw = make_uint2(bfpair(h0, h1), bfpair(h2, h3));
            uint2 low = make_uint2(
                bfpair(__float2bfloat16(v.x - __bfloat162float(h0)),
                       __float2bfloat16(v.y - __bfloat162float(h1))),
                bfpair(__float2bfloat16(v.z - __bfloat162float(h2)),
                       __float2bfloat16(v.w - __bfloat162float(h3))));
            *(uint2*)(smem + SM_AHI + row * 272 + c4 * 8) = hiw;
            *(uint2*)(smem + SM_ALO + row * 272 + c4 * 8) = low;
        }
        __syncthreads();

        // ---- Compute: 3 products x 8 k-steps ----
        float acc[64];
        #pragma unroll
        for (int i = 0; i < 64; i++) acc[i] = 0.f;

        #pragma unroll
        for (int p = 0; p < 3; p++) {
            const uint32_t Ab = sb + ((p < 2) ? SM_AHI : SM_ALO);
            const uint32_t Wb = sb + ((p == 1) ? SM_WLO : SM_WHI);
            #pragma unroll
            for (int ks = 0; ks < 8; ks++) {
                const uint32_t koff = (uint32_t)(ks * 32);   // k0*2 bytes
                uint32_t a0[4], a1[4];
                ldsm_x4(a0[0], a0[1], a0[2], a0[3], Ab + aRel0 + koff);
                ldsm_x4(a1[0], a1[1], a1[2], a1[3], Ab + aRel1 + koff);
                #pragma unroll
                for (int g = 0; g < 4; g++) {
                    uint32_t b0, b1, b2, b3;
                    ldsm_x4(b0, b1, b2, b3, Wb + bRel[g] + koff);
                    mma_bf16(acc + (0 * 8 + 2 * g    ) * 4, a0[0], a0[1], a0[2], a0[3], b0, b1);
                    mma_bf16(acc + (0 * 8 + 2 * g + 1) * 4, a0[0], a0[1], a0[2], a0[3], b2, b3);
                    mma_bf16(acc + (1 * 8 + 2 * g    ) * 4, a1[0], a1[1], a1[2], a1[3], b0, b1);
                    mma_bf16(acc + (1 * 8 + 2 * g + 1) * 4, a1[0], a1[1], a1[2], a1[3], b2, b3);
                }
            }
        }

        // ---- Store (32B-sector coalesced float2 per lane) ----
        #pragma unroll
        for (int mb = 0; mb < 2; mb++) {
            int node0 = tb + mrow + mb * 16 + r;
            #pragma unroll
            for (int nb = 0; nb < 8; nb++) {
                const float* a = acc + (mb * 8 + nb) * 4;
                int d = dbase + nb * 8 + cc;
                if (node0 < BN)
                    *(float2*)(outb + node0 * H + d) = make_float2(a[0], a[1]);
                if (node0 + 8 < BN)
                    *(float2*)(outb + (node0 + 8) * H + d) = make_float2(a[2], a[3]);
            }
        }
        __syncthreads();   // A tile free before next fill
    }
}

// ---------------------------------------------------------------------------
// Gather + residual + relu: h' = relu( (sum_K Y[nbr]) / max(vlen,1) + U )
// (known-good, ~L2-floor)
// ---------------------------------------------------------------------------
extern "C" __global__ void __launch_bounds__(THREADS_GAT)
gather_relu_kernel(const float* __restrict__ Yp, const float* __restrict__ Up,
                   const int* __restrict__ nbr, const int* __restrict__ vlen,
                   float* __restrict__ hout)
{
    const int lane = threadIdx.x & 31;
    const int gw   = (blockIdx.x * THREADS_GAT + threadIdx.x) >> 5;
    const int nw   = (gridDim.x * THREADS_GAT) >> 5;
    const float4* Y4 = (const float4*)Yp;
    const float4* U4 = (const float4*)Up;

    for (int node = gw; node < BN; node += nw) {
        const int boff = (node >= NPB_NODES) ? NPB_NODES : 0;
        int myi = nbr[node * KNB + lane];

        float4 a0 = make_float4(0.f, 0.f, 0.f, 0.f);
        float4 a1 = make_float4(0.f, 0.f, 0.f, 0.f);
        float4 a2 = make_float4(0.f, 0.f, 0.f, 0.f);
        float4 a3 = make_float4(0.f, 0.f, 0.f, 0.f);
        #pragma unroll
        for (int k = 0; k < 8; k++) {
            int i0 = __shfl_sync(0xffffffffu, myi, k);
            int i1 = __shfl_sync(0xffffffffu, myi, k + 8);
            int i2 = __shfl_sync(0xffffffffu, myi, k + 16);
            int i3 = __shfl_sync(0xffffffffu, myi, k + 24);
            float4 v0 = Y4[(boff + i0) * 32 + lane];
            float4 v1 = Y4[(boff + i1) * 32 + lane];
            float4 v2 = Y4[(boff + i2) * 32 + lane];
            float4 v3 = Y4[(boff + i3) * 32 + lane];
            a0.x += v0.x; a0.y += v0.y; a0.z += v0.z; a0.w += v0.w;
            a1.x += v1.x; a1.y += v1.y; a1.z += v1.z; a1.w += v1.w;
            a2.x += v2.x; a2.y += v2.y; a2.z += v2.z; a2.w += v2.w;
            a3.x += v3.x; a3.y += v3.y; a3.z += v3.z; a3.w += v3.w;
        }
        int len = vlen[node];
        float inv = 1.0f / (float)(len > 0 ? len : 1);
        float4 u = U4[node * 32 + lane];
        float4 o;
        o.x = fmaxf((a0.x + a1.x + a2.x + a3.x) * inv + u.x, 0.f);
        o.y = fmaxf((a0.y + a1.y + a2.y + a3.y) * inv + u.y, 0.f);
        o.z = fmaxf((a0.z + a1.z + a2.z + a3.z) * inv + u.z, 0.f);
        o.w = fmaxf((a0.w + a1.w + a2.w + a3.w) * inv + u.w, 0.f);
        ((float4*)hout)[node * 32 + lane] = o;
    }
}

// ---------------------------------------------------------------------------
// Embed: h = (X @ W_embed) / rowsum(X). (unchanged, known-good)
// ---------------------------------------------------------------------------
extern "C" __global__ void __launch_bounds__(THREADS_EMB)
embed_kernel(const float* __restrict__ X, const float* __restrict__ W,
             float* __restrict__ out)
{
    extern __shared__ float sm[];
    float* Wsh = sm;                  // 16384 floats
    float* xs  = sm + 16384;          // 32*128

    const int tid  = threadIdx.x;
    const int lane = tid & 31;
    const int w    = tid >> 5;

    for (int i = tid; i < H * H; i += THREADS_EMB) Wsh[i] = W[i];
    __syncthreads();

    float* xsw = xs + (w * 4) * H;
    const float4* X4 = (const float4*)X;

    const int gw = blockIdx.x * (THREADS_EMB / 32) + w;
    const int nwarps_total = gridDim.x * (THREADS_EMB / 32);
    for (int g = gw; g < BN / 4; g += nwarps_total) {
        const int base = g * 4;
        float inv[4];
        #pragma unroll
        for (int j = 0; j < 4; j++) {
            float4 v = X4[(base + j) * 32 + lane];
            ((float4*)(xsw + j * H))[lane] = v;
            float s = v.x + v.y + v.z + v.w;
            #pragma unroll
            for (int o = 16; o; o >>= 1) s += __shfl_xor_sync(0xffffffffu, s, o);
            inv[j] = 1.0f / s;
        }
        __syncwarp();

        unsigned long long axy[4], azw[4];
        #pragma unroll
        for (int j = 0; j < 4; j++) { axy[j] = 0ull; azw[j] = 0ull; }

        #pragma unroll 2
        for (int f0 = 0; f0 < H; f0 += 4) {
            ulonglong2 wv[4];
            #pragma unroll
            for (int q = 0; q < 4; q++)
                wv[q] = ((const ulonglong2*)(Wsh + (f0 + q) * H))[lane];
            #pragma unroll
            for (int j = 0; j < 4; j++) {
                float4 av = *(const float4*)(xsw + j * H + f0);
                unsigned long long aa;
                PACK2(aa, av.x); FMA2(axy[j], aa, wv[0].x); FMA2(azw[j], aa, wv[0].y);
                PACK2(aa, av.y); FMA2(axy[j], aa, wv[1].x); FMA2(azw[j], aa, wv[1].y);
                PACK2(aa, av.z); FMA2(axy[j], aa, wv[2].x); FMA2(azw[j], aa, wv[2].y);
                PACK2(aa, av.w); FMA2(axy[j], aa, wv[3].x); FMA2(azw[j], aa, wv[3].y);
            }
        }
        #pragma unroll
        for (int j = 0; j < 4; j++) {
            float x, y, z, u;
            UNPACK2(x, y, axy[j]);
            UNPACK2(z, u, azw[j]);
            float4 o = make_float4(x * inv[j], y * inv[j], z * inv[j], u * inv[j]);
            ((float4*)out)[(base + j) * 32 + lane] = o;
        }
        __syncwarp();
    }
}

// ---------------------------------------------------------------------------
// Classifier (unchanged, known-good): z = relu(h@W1+b1); softmax(z@W2+b2)
// ---------------------------------------------------------------------------
extern "C" __global__ void __launch_bounds__(THREADS_CLS)
classifier_kernel(const float* __restrict__ hin,
                  const float* __restrict__ W1, const float* __restrict__ b1,
                  const float* __restrict__ W2, const float* __restrict__ b2,
                  float* __restrict__ out)
{
    extern __shared__ float sm[];
    float* W1sh = sm;
    float* W2sh = W1sh + 16384;
    float* b1sh = W2sh + H * C;
    float* b2sh = b1sh + H;
    float* zsh  = b2sh + C;

    const int tid  = threadIdx.x;
    const int lane = tid & 31;
    const int w    = tid >> 5;

    for (int i = tid; i < H * H; i += THREADS_CLS) W1sh[i] = W1[i];
    for (int i = tid; i < H * C; i += THREADS_CLS) W2sh[i] = W2[i];
    if (tid < H) b1sh[tid] = b1[tid];
    if (tid < C) b2sh[tid] = b2[tid];
    __syncthreads();

    float* zshw = zsh + (w * NPW) * H;
    const float4* h4 = (const float4*)hin;

    const int c2 = 32 + (lane & 7);
    const bool has2 = (lane < 8);

    const int gw = blockIdx.x * NWARPS_CLS + w;
    for (int g = gw; g < NGROUPS; g += TOTAL_WARPS_CLS) {
        const int base = g * NPW;

        #pragma unroll
        for (int n = 0; n < NPW; n++)
            ((float4*)(zshw + n * H))[lane] = h4[(base + n) * 32 + lane];
        __syncwarp();

        unsigned long long axy[NPW], azw[NPW];
        #pragma unroll
        for (int n = 0; n < NPW; n++) { axy[n] = 0ull; azw[n] = 0ull; }

        #pragma unroll 2
        for (int f0 = 0; f0 < H; f0 += 4) {
            ulonglong2 wv[4];
            #pragma unroll
            for (int q = 0; q < 4; q++)
                wv[q] = ((const ulonglong2*)(W1sh + (f0 + q) * H))[lane];
            #pragma unroll
            for (int n = 0; n < NPW; n++) {
                float4 av = *(const float4*)(zshw + n * H + f0);
                unsigned long long aa;
                PACK2(aa, av.x); FMA2(axy[n], aa, wv[0].x); FMA2(azw[n], aa, wv[0].y);
                PACK2(aa, av.y); FMA2(axy[n], aa, wv[1].x); FMA2(azw[n], aa, wv[1].y);
                PACK2(aa, av.z); FMA2(axy[n], aa, wv[2].x); FMA2(azw[n], aa, wv[2].y);
                PACK2(aa, av.w); FMA2(axy[n], aa, wv[3].x); FMA2(azw[n], aa, wv[3].y);
            }
        }

        float4 bb = ((const float4*)b1sh)[lane];
        float4 zreg[NPW];
        #pragma unroll
        for (int n = 0; n < NPW; n++) {
            float x, y, z, u;
            UNPACK2(x, y, axy[n]);
            UNPACK2(z, u, azw[n]);
            zreg[n] = make_float4(fmaxf(x + bb.x, 0.f), fmaxf(y + bb.y, 0.f),
                                  fmaxf(z + bb.z, 0.f), fmaxf(u + bb.w, 0.f));
        }
        __syncwarp();
        #pragma unroll
        for (int n = 0; n < NPW; n++)
            ((float4*)(zshw + n * H))[lane] = zreg[n];
        __syncwarp();

        float l1[NPW], l2[NPW];
        #pragma unroll
        for (int n = 0; n < NPW; n++) { l1[n] = b2sh[lane]; l2[n] = b2sh[c2]; }

        #pragma unroll 2
        for (int f0 = 0; f0 < H; f0 += 4) {
            float w2a[4], w2b[4];
            #pragma unroll
            for (int q = 0; q < 4; q++) {
                w2a[q] = W2sh[(f0 + q) * C + lane];
                w2b[q] = W2sh[(f0 + q) * C + c2];
            }
            #pragma unroll
            for (int n = 0; n < NPW; n++) {
                float4 zv = *(const float4*)(zshw + n * H + f0);
                l1[n] += zv.x * w2a[0] + zv.y * w2a[1];
                l1[n] += zv.z * w2a[2] + zv.w * w2a[3];
                l2[n] += zv.x * w2b[0] + zv.y * w2b[1];
                l2[n] += zv.z * w2b[2] + zv.w * w2b[3];
            }
        }

        #pragma unroll
        for (int n = 0; n < NPW; n++) {
            float m = fmaxf(l1[n], has2 ? l2[n] : -INFINITY);
            #pragma unroll
            for (int o = 16; o; o >>= 1) m = fmaxf(m, __shfl_xor_sync(0xffffffffu, m, o));
            float e1 = __expf(l1[n] - m);
            float e2 = has2 ? __expf(l2[n] - m) : 0.f;
            float s = e1 + e2;
            #pragma unroll
            for (int o = 16; o; o >>= 1) s += __shfl_xor_sync(0xffffffffu, s, o);
            float invs = 1.0f / s;
            out[(base + n) * C + lane] = e1 * invs;
            if (has2) out[(base + n) * C + c2] = e2 * invs;
        }
        __syncwarp();
    }
}

// ---------------------------------------------------------------------------
// Launch
// ---------------------------------------------------------------------------
#define EMBED_SMEM  ((16384 + 32 * H) * 4)
#define CLS_SMEM    ((16384 + H * C + H + C + NWARPS_CLS * NPW * H) * 4)

extern "C" void kernel_launch(void* const* d_in, const int* in_sizes, int n_in,
                              void* d_out, int out_size)
{
    const float* X    = (const float*)d_in[0];
    const int*   nbr  = (const int*)d_in[1];
    const int*   vlen = (const int*)d_in[2];
    const float* We   = (const float*)d_in[3];
    const float* gW   = (const float*)d_in[4];
    const float* gB   = (const float*)d_in[5];
    const float* W1   = (const float*)d_in[6];
    const float* b1   = (const float*)d_in[7];
    const float* W2   = (const float*)d_in[8];
    const float* b2   = (const float*)d_in[9];
    float* out = (float*)d_out;

    (void)in_sizes; (void)n_in; (void)out_size;

    cudaFuncSetAttribute(embed_kernel,      cudaFuncAttributeMaxDynamicSharedMemorySize, EMBED_SMEM);
    cudaFuncSetAttribute(gemm_mma_kernel,   cudaFuncAttributeMaxDynamicSharedMemorySize, GEMM_SMEM);
    cudaFuncSetAttribute(classifier_kernel, cudaFuncAttributeMaxDynamicSharedMemorySize, CLS_SMEM);

    float *h0, *h1, *yb, *ub;
    cudaGetSymbolAddress((void**)&h0, g_h0);
    cudaGetSymbolAddress((void**)&h1, g_h1);
    cudaGetSymbolAddress((void**)&yb, g_y);
    cudaGetSymbolAddress((void**)&ub, g_u);

    embed_kernel<<<296, THREADS_EMB, EMBED_SMEM>>>(X, We, h0);

    gemm_mma_kernel<<<GRID, GT, GEMM_SMEM>>>(h0, gW + 0 * H * H, gB + 0 * H * H, yb, ub);
    gather_relu_kernel<<<296, THREADS_GAT>>>(yb, ub, nbr, vlen, h1);

    gemm_mma_kernel<<<GRID, GT, GEMM_SMEM>>>(h1, gW + 1 * H * H, gB + 1 * H * H, yb, ub);
    gather_relu_kernel<<<296, THREADS_GAT>>>(yb, ub, nbr, vlen, h0);

    gemm_mma_kernel<<<GRID, GT, GEMM_SMEM>>>(h0, gW + 2 * H * H, gB + 2 * H * H, yb, ub);
    gather_relu_kernel<<<296, THREADS_GAT>>>(yb, ub, nbr, vlen, h1);

    classifier_kernel<<<GRID, THREADS_CLS, CLS_SMEM>>>(h1, W1, b1, W2, b2, out);
}

// round 17
// speedup vs baseline: 1.1628x; 1.1628x over previous
#include <cuda_runtime.h>
#include <cuda_bf16.h>
#include <math.h>
#include <stdint.h>

// Problem constants (fixed by setup_inputs)
#define NBATCH 2
#define NPB_NODES 20000
#define BN (NBATCH * NPB_NODES)   // 40000
#define KNB 32
#define H 128
#define C 40
#define NPW 8
#define NGROUPS (BN / NPW)

#define THREADS_EMB 256
#define THREADS_GAT 512
#define THREADS_CLS 512
#define NWARPS_CLS  16
#define GRID 148
#define TOTAL_WARPS_CLS (GRID * NWARPS_CLS)

// Scratch buffers
__device__ float g_h0[BN * H];
__device__ float g_h1[BN * H];
__device__ float g_y [BN * H];
__device__ float g_u [BN * H];

// packed f32x2 helpers (FFMA kernels)
#define FMA2(acc, a, b) asm("fma.rn.f32x2 %0, %1, %2, %0;" : "+l"(acc) : "l"(a), "l"(b))
#define PACK2(d, s)     asm("mov.b64 %0, {%1, %1};" : "=l"(d) : "f"(s))
#define UNPACK2(lo, hi, s) asm("mov.b64 {%0, %1}, %2;" : "=f"(lo), "=f"(hi) : "l"(s))

__device__ __forceinline__ uint32_t smem_to_u32(const void* p) {
    uint32_t a;
    asm("{ .reg .u64 t; cvta.to.shared.u64 t, %1; cvt.u32.u64 %0, t; }" : "=r"(a) : "l"(p));
    return a;
}
__device__ __forceinline__ void ldsm_x4(uint32_t& r0, uint32_t& r1, uint32_t& r2, uint32_t& r3,
                                        uint32_t addr) {
    asm volatile("ldmatrix.sync.aligned.m8n8.x4.shared.b16 {%0,%1,%2,%3}, [%4];"
                 : "=r"(r0), "=r"(r1), "=r"(r2), "=r"(r3) : "r"(addr));
}
__device__ __forceinline__ void mma_bf16(float* c,
                                         uint32_t a0, uint32_t a1, uint32_t a2, uint32_t a3,
                                         uint32_t b0, uint32_t b1) {
    asm volatile("mma.sync.aligned.m16n8k16.row.col.f32.bf16.bf16.f32 "
                 "{%0,%1,%2,%3}, {%4,%5,%6,%7}, {%8,%9}, {%0,%1,%2,%3};"
                 : "+f"(c[0]), "+f"(c[1]), "+f"(c[2]), "+f"(c[3])
                 : "r"(a0), "r"(a1), "r"(a2), "r"(a3), "r"(b0), "r"(b1));
}
__device__ __forceinline__ uint32_t bfpair(__nv_bfloat16 a, __nv_bfloat16 b) {
    __nv_bfloat162 t; t.x = a; t.y = b;
    return *reinterpret_cast<uint32_t*>(&t);
}

// ---------------------------------------------------------------------------
// Tensor GEMM (mma.sync bf16x3, pipelined): Y = h@W, U = h@B.
// Persistent CTAs; tile = 64 nodes x 256 dims; 16 warps, warp tile 16x64.
// Double-buffered A with register prefetch: global loads of tile t+1 issued
// before compute of tile t -> latency hidden; ONE barrier per tile.
// smem rows padded to 272B -> conflict-free ldmatrix.
//   Whi [256][128]bf16 @0       (69632 B)
//   Wlo                 @69632  (69632 B)
//   A bufs (2x hi+lo 17408B)   @139264 .. 208896
// ---------------------------------------------------------------------------
#define GT 512
#define SM_WHI 0
#define SM_WLO 69632
#define SM_A   139264
#define A_HILO 17408               // bytes per (64x272) half-tile
#define A_BUF  (2 * A_HILO)        // hi+lo per buffer
#define GEMM_SMEM (SM_A + 2 * A_BUF)   // 208896

// convert one prefetched float4 into hi/lo bf16 smem slots
__device__ __forceinline__ void a_convert_store(char* smem, int bufbase, int l, float4 v) {
    int row = l >> 5, c4 = l & 31;
    __nv_bfloat16 h0 = __float2bfloat16(v.x), h1 = __float2bfloat16(v.y);
    __nv_bfloat16 h2 = __float2bfloat16(v.z), h3 = __float2bfloat16(v.w);
    uint2 hiw = make_uint2(bfpair(h0, h1), bfpair(h2, h3));
    uint2 low = make_uint2(
        bfpair(__float2bfloat16(v.x - __bfloat162float(h0)),
               __float2bfloat16(v.y - __bfloat162float(h1))),
        bfpair(__float2bfloat16(v.z - __bfloat162float(h2)),
               __float2bfloat16(v.w - __bfloat162float(h3))));
    *(uint2*)(smem + bufbase + row * 272 + c4 * 8) = hiw;
    *(uint2*)(smem + bufbase + A_HILO + row * 272 + c4 * 8) = low;
}

extern "C" __global__ void __launch_bounds__(GT, 1)
gemm_mma_kernel(const float* __restrict__ hin,
                const float* __restrict__ Wp, const float* __restrict__ Bp,
                float* __restrict__ Yp, float* __restrict__ Up)
{
    extern __shared__ char smem[];
    const uint32_t sb = smem_to_u32(smem);
    const int tid  = threadIdx.x;
    const int lane = tid & 31;
    const int w    = tid >> 5;

    // ---- Stage weights as K-major bf16 hi/lo: Wop[d][k]; d<128 = W(Y), d>=128 = B(U)
    for (int l = tid; l < 128 * 128; l += GT) {
        int k = l >> 7, d = l & 127;
        float wv = Wp[l];
        __nv_bfloat16 hi = __float2bfloat16(wv);
        *(__nv_bfloat16*)(smem + SM_WHI + d * 272 + k * 2) = hi;
        *(__nv_bfloat16*)(smem + SM_WLO + d * 272 + k * 2) =
            __float2bfloat16(wv - __bfloat162float(hi));
        float bv = Bp[l];
        hi = __float2bfloat16(bv);
        *(__nv_bfloat16*)(smem + SM_WHI + (128 + d) * 272 + k * 2) = hi;
        *(__nv_bfloat16*)(smem + SM_WLO + (128 + d) * 272 + k * 2) =
            __float2bfloat16(bv - __bfloat162float(hi));
    }

    const float4* h4 = (const float4*)hin;
    const int mrow = (w & 3) * 16;     // warp m offset within 64-node tile
    const int ncol = (w >> 2) * 64;    // warp n offset (0,64 -> Y; 128,192 -> U)

    // per-lane ldmatrix relative offsets (within a hi/lo half-tile)
    const uint32_t aRel = (uint32_t)((mrow + ((lane >> 3) & 1) * 8 + (lane & 7)) * 272
                                     + (lane >> 4) * 16);
    uint32_t bRel[4];
    #pragma unroll
    for (int g = 0; g < 4; g++)
        bRel[g] = (uint32_t)((ncol + g * 16 + ((lane >> 4) & 1) * 8 + (lane & 7)) * 272
                             + ((lane >> 3) & 1) * 16);

    float* const outb = (ncol < 128) ? Yp : Up;
    const int dbase = ncol & 127;
    const int r = lane >> 2, cc = (lane & 3) * 2;

    const int stride = GRID * 64;
    int tb = blockIdx.x * 64;

    // ---- Prologue: stage first tile into buffer 0 ----
    #pragma unroll
    for (int i = 0; i < 4; i++) {
        int l = tid + i * GT;
        a_convert_store(smem, SM_A, l, h4[(tb + (l >> 5)) * 32 + (l & 31)]);
    }
    __syncthreads();

    int cur = 0;
    for (; tb < BN; tb += stride) {
        const int tbn = tb + stride;
        const bool more = (tbn < BN);

        // (1) prefetch next tile's A into registers (latency hidden by compute)
        float4 pf[4];
        if (more) {
            #pragma unroll
            for (int i = 0; i < 4; i++) {
                int l = tid + i * GT;
                pf[i] = h4[(tbn + (l >> 5)) * 32 + (l & 31)];
            }
        }

        // (2) compute current tile: 3 products x 8 k-steps
        const uint32_t Abase = sb + SM_A + cur * A_BUF;
        float acc[32];
        #pragma unroll
        for (int i = 0; i < 32; i++) acc[i] = 0.f;

        #pragma unroll
        for (int p = 0; p < 3; p++) {
            const uint32_t Ab = Abase + ((p < 2) ? 0u : (uint32_t)A_HILO);
            const uint32_t Wb = sb + ((p == 1) ? SM_WLO : SM_WHI);
            #pragma unroll
            for (int ks = 0; ks < 8; ks++) {
                const uint32_t koff = (uint32_t)(ks * 32);
                uint32_t a0, a1, a2, a3;
                ldsm_x4(a0, a1, a2, a3, Ab + aRel + koff);
                #pragma unroll
                for (int g = 0; g < 4; g++) {
                    uint32_t b0, b1, b2, b3;
                    ldsm_x4(b0, b1, b2, b3, Wb + bRel[g] + koff);
                    mma_bf16(acc + (2 * g    ) * 4, a0, a1, a2, a3, b0, b1);
                    mma_bf16(acc + (2 * g + 1) * 4, a0, a1, a2, a3, b2, b3);
                }
            }
        }

        // (3) store D (sector-coalesced float2 per lane)
        {
            int node0 = tb + mrow + r;
            #pragma unroll
            for (int nb = 0; nb < 8; nb++) {
                const float* a = acc + nb * 4;
                int d = dbase + nb * 8 + cc;
                *(float2*)(outb + node0 * H + d)       = make_float2(a[0], a[1]);
                *(float2*)(outb + (node0 + 8) * H + d) = make_float2(a[2], a[3]);
            }
        }

        if (!more) break;

        // (4) convert prefetched regs into the other buffer; one barrier/tile
        {
            const int nb = SM_A + (cur ^ 1) * A_BUF;
            #pragma unroll
            for (int i = 0; i < 4; i++)
                a_convert_store(smem, nb, tid + i * GT, pf[i]);
        }
        __syncthreads();
        cur ^= 1;
    }
}

// ---------------------------------------------------------------------------
// Gather + residual + relu: h' = relu( (sum_K Y[nbr]) / max(vlen,1) + U )
// (known-good, ~L2-floor)
// ---------------------------------------------------------------------------
extern "C" __global__ void __launch_bounds__(THREADS_GAT)
gather_relu_kernel(const float* __restrict__ Yp, const float* __restrict__ Up,
                   const int* __restrict__ nbr, const int* __restrict__ vlen,
                   float* __restrict__ hout)
{
    const int lane = threadIdx.x & 31;
    const int gw   = (blockIdx.x * THREADS_GAT + threadIdx.x) >> 5;
    const int nw   = (gridDim.x * THREADS_GAT) >> 5;
    const float4* Y4 = (const float4*)Yp;
    const float4* U4 = (const float4*)Up;

    for (int node = gw; node < BN; node += nw) {
        const int boff = (node >= NPB_NODES) ? NPB_NODES : 0;
        int myi = nbr[node * KNB + lane];

        float4 a0 = make_float4(0.f, 0.f, 0.f, 0.f);
        float4 a1 = make_float4(0.f, 0.f, 0.f, 0.f);
        float4 a2 = make_float4(0.f, 0.f, 0.f, 0.f);
        float4 a3 = make_float4(0.f, 0.f, 0.f, 0.f);
        #pragma unroll
        for (int k = 0; k < 8; k++) {
            int i0 = __shfl_sync(0xffffffffu, myi, k);
            int i1 = __shfl_sync(0xffffffffu, myi, k + 8);
            int i2 = __shfl_sync(0xffffffffu, myi, k + 16);
            int i3 = __shfl_sync(0xffffffffu, myi, k + 24);
            float4 v0 = Y4[(boff + i0) * 32 + lane];
            float4 v1 = Y4[(boff + i1) * 32 + lane];
            float4 v2 = Y4[(boff + i2) * 32 + lane];
            float4 v3 = Y4[(boff + i3) * 32 + lane];
            a0.x += v0.x; a0.y += v0.y; a0.z += v0.z; a0.w += v0.w;
            a1.x += v1.x; a1.y += v1.y; a1.z += v1.z; a1.w += v1.w;
            a2.x += v2.x; a2.y += v2.y; a2.z += v2.z; a2.w += v2.w;
            a3.x += v3.x; a3.y += v3.y; a3.z += v3.z; a3.w += v3.w;
        }
        int len = vlen[node];
        float inv = 1.0f / (float)(len > 0 ? len : 1);
        float4 u = U4[node * 32 + lane];
        float4 o;
        o.x = fmaxf((a0.x + a1.x + a2.x + a3.x) * inv + u.x, 0.f);
        o.y = fmaxf((a0.y + a1.y + a2.y + a3.y) * inv + u.y, 0.f);
        o.z = fmaxf((a0.z + a1.z + a2.z + a3.z) * inv + u.z, 0.f);
        o.w = fmaxf((a0.w + a1.w + a2.w + a3.w) * inv + u.w, 0.f);
        ((float4*)hout)[node * 32 + lane] = o;
    }
}

// ---------------------------------------------------------------------------
// Embed: h = (X @ W_embed) / rowsum(X). (unchanged, known-good)
// ---------------------------------------------------------------------------
extern "C" __global__ void __launch_bounds__(THREADS_EMB)
embed_kernel(const float* __restrict__ X, const float* __restrict__ W,
             float* __restrict__ out)
{
    extern __shared__ float sm[];
    float* Wsh = sm;                  // 16384 floats
    float* xs  = sm + 16384;          // 32*128

    const int tid  = threadIdx.x;
    const int lane = tid & 31;
    const int w    = tid >> 5;

    for (int i = tid; i < H * H; i += THREADS_EMB) Wsh[i] = W[i];
    __syncthreads();

    float* xsw = xs + (w * 4) * H;
    const float4* X4 = (const float4*)X;

    const int gw = blockIdx.x * (THREADS_EMB / 32) + w;
    const int nwarps_total = gridDim.x * (THREADS_EMB / 32);
    for (int g = gw; g < BN / 4; g += nwarps_total) {
        const int base = g * 4;
        float inv[4];
        #pragma unroll
        for (int j = 0; j < 4; j++) {
            float4 v = X4[(base + j) * 32 + lane];
            ((float4*)(xsw + j * H))[lane] = v;
            float s = v.x + v.y + v.z + v.w;
            #pragma unroll
            for (int o = 16; o; o >>= 1) s += __shfl_xor_sync(0xffffffffu, s, o);
            inv[j] = 1.0f / s;
        }
        __syncwarp();

        unsigned long long axy[4], azw[4];
        #pragma unroll
        for (int j = 0; j < 4; j++) { axy[j] = 0ull; azw[j] = 0ull; }

        #pragma unroll 2
        for (int f0 = 0; f0 < H; f0 += 4) {
            ulonglong2 wv[4];
            #pragma unroll
            for (int q = 0; q < 4; q++)
                wv[q] = ((const ulonglong2*)(Wsh + (f0 + q) * H))[lane];
            #pragma unroll
            for (int j = 0; j < 4; j++) {
                float4 av = *(const float4*)(xsw + j * H + f0);
                unsigned long long aa;
                PACK2(aa, av.x); FMA2(axy[j], aa, wv[0].x); FMA2(azw[j], aa, wv[0].y);
                PACK2(aa, av.y); FMA2(axy[j], aa, wv[1].x); FMA2(azw[j], aa, wv[1].y);
                PACK2(aa, av.z); FMA2(axy[j], aa, wv[2].x); FMA2(azw[j], aa, wv[2].y);
                PACK2(aa, av.w); FMA2(axy[j], aa, wv[3].x); FMA2(azw[j], aa, wv[3].y);
            }
        }
        #pragma unroll
        for (int j = 0; j < 4; j++) {
            float x, y, z, u;
            UNPACK2(x, y, axy[j]);
            UNPACK2(z, u, azw[j]);
            float4 o = make_float4(x * inv[j], y * inv[j], z * inv[j], u * inv[j]);
            ((float4*)out)[(base + j) * 32 + lane] = o;
        }
        __syncwarp();
    }
}

// ---------------------------------------------------------------------------
// Classifier (unchanged, known-good): z = relu(h@W1+b1); softmax(z@W2+b2)
// ---------------------------------------------------------------------------
extern "C" __global__ void __launch_bounds__(THREADS_CLS)
classifier_kernel(const float* __restrict__ hin,
                  const float* __restrict__ W1, const float* __restrict__ b1,
                  const float* __restrict__ W2, const float* __restrict__ b2,
                  float* __restrict__ out)
{
    extern __shared__ float sm[];
    float* W1sh = sm;
    float* W2sh = W1sh + 16384;
    float* b1sh = W2sh + H * C;
    float* b2sh = b1sh + H;
    float* zsh  = b2sh + C;

    const int tid  = threadIdx.x;
    const int lane = tid & 31;
    const int w    = tid >> 5;

    for (int i = tid; i < H * H; i += THREADS_CLS) W1sh[i] = W1[i];
    for (int i = tid; i < H * C; i += THREADS_CLS) W2sh[i] = W2[i];
    if (tid < H) b1sh[tid] = b1[tid];
    if (tid < C) b2sh[tid] = b2[tid];
    __syncthreads();

    float* zshw = zsh + (w * NPW) * H;
    const float4* h4 = (const float4*)hin;

    const int c2 = 32 + (lane & 7);
    const bool has2 = (lane < 8);

    const int gw = blockIdx.x * NWARPS_CLS + w;
    for (int g = gw; g < NGROUPS; g += TOTAL_WARPS_CLS) {
        const int base = g * NPW;

        #pragma unroll
        for (int n = 0; n < NPW; n++)
            ((float4*)(zshw + n * H))[lane] = h4[(base + n) * 32 + lane];
        __syncwarp();

        unsigned long long axy[NPW], azw[NPW];
        #pragma unroll
        for (int n = 0; n < NPW; n++) { axy[n] = 0ull; azw[n] = 0ull; }

        #pragma unroll 2
        for (int f0 = 0; f0 < H; f0 += 4) {
            ulonglong2 wv[4];
            #pragma unroll
            for (int q = 0; q < 4; q++)
                wv[q] = ((const ulonglong2*)(W1sh + (f0 + q) * H))[lane];
            #pragma unroll
            for (int n = 0; n < NPW; n++) {
                float4 av = *(const float4*)(zshw + n * H + f0);
                unsigned long long aa;
                PACK2(aa, av.x); FMA2(axy[n], aa, wv[0].x); FMA2(azw[n], aa, wv[0].y);
                PACK2(aa, av.y); FMA2(axy[n], aa, wv[1].x); FMA2(azw[n], aa, wv[1].y);
                PACK2(aa, av.z); FMA2(axy[n], aa, wv[2].x); FMA2(azw[n], aa, wv[2].y);
                PACK2(aa, av.w); FMA2(axy[n], aa, wv[3].x); FMA2(azw[n], aa, wv[3].y);
            }
        }

        float4 bb = ((const float4*)b1sh)[lane];
        float4 zreg[NPW];
        #pragma unroll
        for (int n = 0; n < NPW; n++) {
            float x, y, z, u;
            UNPACK2(x, y, axy[n]);
            UNPACK2(z, u, azw[n]);
            zreg[n] = make_float4(fmaxf(x + bb.x, 0.f), fmaxf(y + bb.y, 0.f),
                                  fmaxf(z + bb.z, 0.f), fmaxf(u + bb.w, 0.f));
        }
        __syncwarp();
        #pragma unroll
        for (int n = 0; n < NPW; n++)
            ((float4*)(zshw + n * H))[lane] = zreg[n];
        __syncwarp();

        float l1[NPW], l2[NPW];
        #pragma unroll
        for (int n = 0; n < NPW; n++) { l1[n] = b2sh[lane]; l2[n] = b2sh[c2]; }

        #pragma unroll 2
        for (int f0 = 0; f0 < H; f0 += 4) {
            float w2a[4], w2b[4];
            #pragma unroll
            for (int q = 0; q < 4; q++) {
                w2a[q] = W2sh[(f0 + q) * C + lane];
                w2b[q] = W2sh[(f0 + q) * C + c2];
            }
            #pragma unroll
            for (int n = 0; n < NPW; n++) {
                float4 zv = *(const float4*)(zshw + n * H + f0);
                l1[n] += zv.x * w2a[0] + zv.y * w2a[1];
                l1[n] += zv.z * w2a[2] + zv.w * w2a[3];
                l2[n] += zv.x * w2b[0] + zv.y * w2b[1];
                l2[n] += zv.z * w2b[2] + zv.w * w2b[3];
            }
        }

        #pragma unroll
        for (int n = 0; n < NPW; n++) {
            float m = fmaxf(l1[n], has2 ? l2[n] : -INFINITY);
            #pragma unroll
            for (int o = 16; o; o >>= 1) m = fmaxf(m, __shfl_xor_sync(0xffffffffu, m, o));
            float e1 = __expf(l1[n] - m);
            float e2 = has2 ? __expf(l2[n] - m) : 0.f;
            float s = e1 + e2;
            #pragma unroll
            for (int o = 16; o; o >>= 1) s += __shfl_xor_sync(0xffffffffu, s, o);
            float invs = 1.0f / s;
            out[(base + n) * C + lane] = e1 * invs;
            if (has2) out[(base + n) * C + c2] = e2 * invs;
        }
        __syncwarp();
    }
}

// ---------------------------------------------------------------------------
// Launch
// ---------------------------------------------------------------------------
#define EMBED_SMEM  ((16384 + 32 * H) * 4)
#define CLS_SMEM    ((16384 + H * C + H + C + NWARPS_CLS * NPW * H) * 4)

extern "C" void kernel_launch(void* const* d_in, const int* in_sizes, int n_in,
                              void* d_out, int out_size)
{
    const float* X    = (const float*)d_in[0];
    const int*   nbr  = (const int*)d_in[1];
    const int*   vlen = (const int*)d_in[2];
    const float* We   = (const float*)d_in[3];
    const float* gW   = (const float*)d_in[4];
    const float* gB   = (const float*)d_in[5];
    const float* W1   = (const float*)d_in[6];
    const float* b1   = (const float*)d_in[7];
    const float* W2   = (const float*)d_in[8];
    const float* b2   = (const float*)d_in[9];
    float* out = (float*)d_out;

    (void)in_sizes; (void)n_in; (void)out_size;

    cudaFuncSetAttribute(embed_kernel,      cudaFuncAttributeMaxDynamicSharedMemorySize, EMBED_SMEM);
    cudaFuncSetAttribute(gemm_mma_kernel,   cudaFuncAttributeMaxDynamicSharedMemorySize, GEMM_SMEM);
    cudaFuncSetAttribute(classifier_kernel, cudaFuncAttributeMaxDynamicSharedMemorySize, CLS_SMEM);

    float *h0, *h1, *yb, *ub;
    cudaGetSymbolAddress((void**)&h0, g_h0);
    cudaGetSymbolAddress((void**)&h1, g_h1);
    cudaGetSymbolAddress((void**)&yb, g_y);
    cudaGetSymbolAddress((void**)&ub, g_u);

    embed_kernel<<<296, THREADS_EMB, EMBED_SMEM>>>(X, We, h0);

    gemm_mma_kernel<<<GRID, GT, GEMM_SMEM>>>(h0, gW + 0 * H * H, gB + 0 * H * H, yb, ub);
    gather_relu_kernel<<<296, THREADS_GAT>>>(yb, ub, nbr, vlen, h1);

    gemm_mma_kernel<<<GRID, GT, GEMM_SMEM>>>(h1, gW + 1 * H * H, gB + 1 * H * H, yb, ub);
    gather_relu_kernel<<<296, THREADS_GAT>>>(yb, ub, nbr, vlen, h0);

    gemm_mma_kernel<<<GRID, GT, GEMM_SMEM>>>(h0, gW + 2 * H * H, gB + 2 * H * H, yb, ub);
    gather_relu_kernel<<<296, THREADS_GAT>>>(yb, ub, nbr, vlen, h1);

    classifier_kernel<<<GRID, THREADS_CLS, CLS_SMEM>>>(h1, W1, b1, W2, b2, out);
}